// round 9
// baseline (speedup 1.0000x reference)
#include <cuda_runtime.h>
#include <cuda_bf16.h>
#include <cstdint>

typedef unsigned long long ull;

// ---------------------------------------------------------------------------
// Scratch (bf16 hi/lo-split GEMM operands, K=64 per row = 128 B)
//   g_A[m][64]: [Phi(16) | Phi(16) | Plo(16) | 1,1,0...]
//   g_W[v][64]: [Whi(16) | Wlo(16) | Whi(16) | bias_hi,bias_lo,0...]
// D = Phi*Whi + Phi*Wlo + Plo*Whi + bias  (fp32 accum; lo*lo term ~2^-18)
// ---------------------------------------------------------------------------
__device__ __align__(16) __nv_bfloat16 g_A[4096 * 64];
__device__ __align__(16) __nv_bfloat16 g_W[32000 * 64];

__device__ __forceinline__ uint32_t smem_u32(const void* p) {
    uint32_t a;
    asm("{ .reg .u64 t; cvta.to.shared.u64 t, %1; cvt.u32.u64 %0, t; }"
        : "=r"(a) : "l"(p));
    return a;
}
__device__ __forceinline__ void bf16_split(float x, __nv_bfloat16& hi, __nv_bfloat16& lo) {
    hi = __float2bfloat16(x);
    lo = __float2bfloat16(x - __bfloat162float(hi));
}

// ---------------------------------------------------------------------------
// Kernel 1: per-token quantum circuit -> g_A rows (bf16 split layout)
// ---------------------------------------------------------------------------
__global__ void prep_kernel(const int* __restrict__ ids,
                            const int* __restrict__ mask,
                            const float* __restrict__ We,
                            const float* __restrict__ gates,
                            int BS, int depth, int S, int B) {
    __shared__ float sg[2 * 256];
    for (int i = threadIdx.x; i < depth * 256; i += blockDim.x) sg[i] = gates[i];
    __syncthreads();

    int m = blockIdx.x * blockDim.x + threadIdx.x;
    if (m >= BS) return;

    int tok = ids[m];
    float e[16], st[16];
    const float4* wr = (const float4*)(We + (size_t)tok * 16);
#pragma unroll
    for (int q = 0; q < 4; q++) {
        float4 v = wr[q];
        e[4*q+0] = v.x; e[4*q+1] = v.y; e[4*q+2] = v.z; e[4*q+3] = v.w;
    }
    float nrm = 0.f;
#pragma unroll
    for (int k = 0; k < 16; k++) nrm += e[k] * e[k];
    float inv = 1.f / (sqrtf(nrm) + 1e-12f);
#pragma unroll
    for (int k = 0; k < 16; k++) { e[k] *= inv; st[k] = e[k]; }

    for (int l = 0; l < depth; l++) {
        float tmp[16];
#pragma unroll
        for (int o = 0; o < 16; o++) {
            float acc = 0.f;
#pragma unroll
            for (int d = 0; d < 16; d++) acc += st[d] * sg[l*256 + o*16 + d];
            tmp[o] = acc;
        }
        float s2 = 0.f;
#pragma unroll
        for (int o = 0; o < 16; o++) {
            float x = tmp[o] * (0.99f * 0.99f) + (0.01f / 16.f);
            st[o] = x; s2 += x * x;
        }
        inv = 1.f / (sqrtf(s2) + 1e-12f);
#pragma unroll
        for (int o = 0; o < 16; o++) st[o] *= inv;
    }
#pragma unroll
    for (int k = 0; k < 16; k++) st[k] = st[k] * 0.99f + (0.01f / 16.f);

    int s = m % S;
    bool ap = true;
    for (int b = 0; b < B; b++) ap = ap && (mask[b * S + s] != 0);

    __nv_bfloat16* row = g_A + (size_t)m * 64;
#pragma unroll
    for (int k = 0; k < 16; k++) {
        float v = ap ? st[k] : e[k];
        __nv_bfloat16 hi, lo; bf16_split(v, hi, lo);
        row[k] = hi; row[16 + k] = hi; row[32 + k] = lo;
    }
    row[48] = __float2bfloat16(1.0f);
    row[49] = __float2bfloat16(1.0f);
#pragma unroll
    for (int k = 50; k < 64; k++) row[k] = __float2bfloat16(0.0f);
}

// ---------------------------------------------------------------------------
// Kernel 1b: W_out + bias -> g_W rows (bf16 split layout)
// ---------------------------------------------------------------------------
__global__ void wconv_kernel(const float* __restrict__ Wout,
                             const float* __restrict__ bout, int V) {
    int v = blockIdx.x * blockDim.x + threadIdx.x;
    if (v >= V) return;
    const float* wr = Wout + (size_t)v * 16;
    __nv_bfloat16* row = g_W + (size_t)v * 64;
#pragma unroll
    for (int k = 0; k < 16; k++) {
        __nv_bfloat16 hi, lo; bf16_split(wr[k], hi, lo);
        row[k] = hi; row[16 + k] = lo; row[32 + k] = hi;
    }
    __nv_bfloat16 bh, bl; bf16_split(bout[v], bh, bl);
    row[48] = bh; row[49] = bl;
#pragma unroll
    for (int k = 50; k < 64; k++) row[k] = __float2bfloat16(0.0f);
}

// ---------------------------------------------------------------------------
// Kernel 2: HMMA bf16 GEMM (mma.sync.m16n8k16), tile 128x128, 8 warps (2x4).
// smem tiles use 72-bf16 (144B) row stride (ldmatrix conflict-free).
// Epilogue: STAGED. Fragments -> smem (reusing tile smem, 64-row passes,
// stride 132 floats) -> full-row coalesced STG.128 (warp = 512B contiguous,
// 4 wavefronts per 512B vs 8 per 256B for direct fragment stores).
// ---------------------------------------------------------------------------
#define SA 72        // tile smem row stride in bf16
#define SSTG 132     // stage row stride in floats

__global__ __launch_bounds__(256)
void hmma_gemm_kernel(float* __restrict__ out, int V) {
    __shared__ __align__(16) char smem_buf[2 * 128 * SA * 2];  // 36864 B
    __nv_bfloat16* sA = (__nv_bfloat16*)smem_buf;
    __nv_bfloat16* sB = sA + 128 * SA;
    float* stage = (float*)smem_buf;          // union; 64*132*4 = 33792 B

    int tid = threadIdx.x, wid = tid >> 5, lane = tid & 31;
    int row0 = blockIdx.y * 128;
    int v0   = blockIdx.x * 128;

    // cooperative tile loads: 128 rows x 64 bf16 = 1024 uint4 each
    {
        const uint4* srcA = (const uint4*)(g_A + (size_t)row0 * 64);
        const uint4* srcB = (const uint4*)(g_W + (size_t)v0 * 64);
#pragma unroll
        for (int i = tid; i < 1024; i += 256) {
            int r = i >> 3, c = i & 7;
            *(uint4*)(sA + r * SA + c * 8) = srcA[i];
            *(uint4*)(sB + r * SA + c * 8) = srcB[i];
        }
    }
    __syncthreads();

    int wm = wid >> 2;        // 0..1 : 64-row half
    int wn = wid & 3;         // 0..3 : 32-col quarter

    // ldmatrix lane->address mapping
    int aRowL = (lane & 7) + ((lane >> 3) & 1) * 8;
    int aColH = ((lane >> 4) & 1) * 8;
    int lb = lane & 15;
    int bRowL = lb & 7;
    int bColH = ((lb >> 3) & 1) * 8;

    uint32_t aBase = smem_u32(sA);
    uint32_t bBase = smem_u32(sB);

    float c[4][4][4];
#pragma unroll
    for (int mt = 0; mt < 4; mt++)
#pragma unroll
        for (int nt = 0; nt < 4; nt++)
#pragma unroll
            for (int j = 0; j < 4; j++) c[mt][nt][j] = 0.f;

#pragma unroll
    for (int k = 0; k < 4; k++) {
        uint32_t a[4][4], b[4][2];
#pragma unroll
        for (int mt = 0; mt < 4; mt++) {
            uint32_t addr = aBase +
                (uint32_t)(((wm * 64 + mt * 16 + aRowL) * SA + k * 16 + aColH) * 2);
            asm volatile("ldmatrix.sync.aligned.m8n8.x4.shared.b16 {%0,%1,%2,%3}, [%4];"
                         : "=r"(a[mt][0]), "=r"(a[mt][1]), "=r"(a[mt][2]), "=r"(a[mt][3])
                         : "r"(addr));
        }
#pragma unroll
        for (int nt = 0; nt < 4; nt++) {
            uint32_t addr = bBase +
                (uint32_t)(((wn * 32 + nt * 8 + bRowL) * SA + k * 16 + bColH) * 2);
            asm volatile("ldmatrix.sync.aligned.m8n8.x2.shared.b16 {%0,%1}, [%2];"
                         : "=r"(b[nt][0]), "=r"(b[nt][1]) : "r"(addr));
        }
#pragma unroll
        for (int mt = 0; mt < 4; mt++)
#pragma unroll
            for (int nt = 0; nt < 4; nt++)
                asm volatile(
                    "mma.sync.aligned.m16n8k16.row.col.f32.bf16.bf16.f32 "
                    "{%0,%1,%2,%3}, {%4,%5,%6,%7}, {%8,%9}, {%0,%1,%2,%3};"
                    : "+f"(c[mt][nt][0]), "+f"(c[mt][nt][1]),
                      "+f"(c[mt][nt][2]), "+f"(c[mt][nt][3])
                    : "r"(a[mt][0]), "r"(a[mt][1]), "r"(a[mt][2]), "r"(a[mt][3]),
                      "r"(b[nt][0]), "r"(b[nt][1]));
    }

    // ---------------- staged epilogue: two 64-row passes --------------------
    int rr = lane >> 2, q2 = (lane & 3) * 2;
#pragma unroll 1
    for (int p = 0; p < 2; p++) {
        __syncthreads();   // tile smem / previous pass reads complete
        if (wm == p) {
#pragma unroll
            for (int mt = 0; mt < 4; mt++) {
                int srow = mt * 16 + rr;
#pragma unroll
                for (int nt = 0; nt < 4; nt++) {
                    int scol = wn * 32 + nt * 8 + q2;
                    *(float2*)(stage + srow * SSTG + scol) =
                        make_float2(c[mt][nt][0], c[mt][nt][1]);
                    *(float2*)(stage + (srow + 8) * SSTG + scol) =
                        make_float2(c[mt][nt][2], c[mt][nt][3]);
                }
            }
        }
        __syncthreads();
        // coalesced store: 64 rows x 128 cols = 2048 float4, 8 per thread
        float* obase = out + (size_t)(row0 + p * 64) * V + v0;
#pragma unroll
        for (int j = 0; j < 8; j++) {
            int idx = tid + 256 * j;
            int row = idx >> 5, c4 = (idx & 31) * 4;
            float4 v = *(float4*)(stage + row * SSTG + c4);
            __stcs((float4*)(obase + (size_t)row * V + c4), v);
        }
    }
}

// ---------------------------------------------------------------------------
// Launch
// ---------------------------------------------------------------------------
extern "C" void kernel_launch(void* const* d_in, const int* in_sizes, int n_in,
                              void* d_out, int out_size) {
    const int*   ids   = (const int*)d_in[0];
    const int*   mask  = (const int*)d_in[1];
    const float* We    = (const float*)d_in[2];
    const float* gates = (const float*)d_in[3];
    const float* Wout  = (const float*)d_in[4];
    const float* bout  = (const float*)d_in[5];
    float* out = (float*)d_out;

    int BS    = in_sizes[0];          // 4096
    int V     = in_sizes[5];          // 32000
    int depth = in_sizes[3] / 256;    // 2
    int S     = 2048;
    int B     = BS / S;

    // spread prep over all SMs (was 32 CTAs -> 9.7us)
    prep_kernel<<<BS / 32, 32>>>(ids, mask, We, gates, BS, depth, S, B);
    wconv_kernel<<<(V + 255) / 256, 256>>>(Wout, bout, V);

    dim3 grid(V / 128, BS / 128);     // (250, 32)
    hmma_gemm_kernel<<<grid, 256>>>(out, V);
}

// round 10
// speedup vs baseline: 1.5535x; 1.5535x over previous
#include <cuda_runtime.h>
#include <cuda_bf16.h>
#include <cstdint>

typedef unsigned long long ull;

// ---------------------------------------------------------------------------
// Scratch (bf16 hi/lo-split GEMM operands, K=64 per row = 128 B)
//   g_A[m][64]: [Phi(16) | Phi(16) | Plo(16) | 1,1,0...]
//   g_W[v][64]: [Whi(16) | Wlo(16) | Whi(16) | bias_hi,bias_lo,0...]
// D = Phi*Whi + Phi*Wlo + Plo*Whi + bias  (fp32 accum; lo*lo term ~2^-18)
// ---------------------------------------------------------------------------
__device__ __align__(16) __nv_bfloat16 g_A[4096 * 64];
__device__ __align__(16) __nv_bfloat16 g_W[32000 * 64];

__device__ __forceinline__ uint32_t smem_u32(const void* p) {
    uint32_t a;
    asm("{ .reg .u64 t; cvta.to.shared.u64 t, %1; cvt.u32.u64 %0, t; }"
        : "=r"(a) : "l"(p));
    return a;
}
__device__ __forceinline__ void bf16_split(float x, __nv_bfloat16& hi, __nv_bfloat16& lo) {
    hi = __float2bfloat16(x);
    lo = __float2bfloat16(x - __bfloat162float(hi));
}

// ---------------------------------------------------------------------------
// Kernel 1 (fused): blocks [0, prepBlocks): half-warp-per-token circuit -> g_A
//                   blocks [prepBlocks, ...): W_out+bias conversion  -> g_W
// Prep: lane k (of 16) owns state element k. Gate matmul via shfl.idx against
// transposed gates in smem (lanes read 16 consecutive words = broadcast-free,
// conflict-free). Norms via 4 butterfly shuffles. 16 tokens per 256-thr block.
// ---------------------------------------------------------------------------
__global__ __launch_bounds__(256)
void prep_all_kernel(const int* __restrict__ ids,
                     const int* __restrict__ mask,
                     const float* __restrict__ We,
                     const float* __restrict__ gates,
                     const float* __restrict__ Wout,
                     const float* __restrict__ bout,
                     int BS, int depth, int S, int B, int V, int prepBlocks) {
    if (blockIdx.x < (unsigned)prepBlocks) {
        __shared__ float sgt[2 * 256];   // transposed: sgt[l*256 + d*16 + o]
        for (int i = threadIdx.x; i < depth * 256; i += 256) {
            int l = i >> 8, r = i & 255, o = r >> 4, d = r & 15;
            sgt[l * 256 + d * 16 + o] = gates[i];
        }
        __syncthreads();

        int lane = threadIdx.x & 31, wid = threadIdx.x >> 5;
        int half = lane >> 4, k = lane & 15;
        int m = blockIdx.x * 16 + wid * 2 + half;
        if (m >= BS) return;

        int tok = ids[m];
        float e = We[(size_t)tok * 16 + k];
        // normalize: x / (||x|| + 1e-12)
        float s = e * e;
#pragma unroll
        for (int off = 8; off; off >>= 1)
            s += __shfl_xor_sync(0xffffffffu, s, off, 16);
        e *= 1.f / (sqrtf(s) + 1e-12f);
        float st = e;

        for (int l = 0; l < depth; l++) {
            float acc = 0.f;
            const float* g = sgt + l * 256 + k;
#pragma unroll
            for (int d = 0; d < 16; d++) {
                float sd = __shfl_sync(0xffffffffu, st, d, 16);
                acc = fmaf(sd, g[d * 16], acc);
            }
            // (1-DECOHERENCE)*(1-DEPOL)*x + DEPOL/dim
            float x = acc * (0.99f * 0.99f) + (0.01f / 16.f);
            float s2 = x * x;
#pragma unroll
            for (int off = 8; off; off >>= 1)
                s2 += __shfl_xor_sync(0xffffffffu, s2, off, 16);
            st = x * (1.f / (sqrtf(s2) + 1e-12f));
        }
        st = st * 0.99f + (0.01f / 16.f);

        int s_pos = m % S;
        bool ap = true;
        for (int b = 0; b < B; b++) ap = ap && (mask[b * S + s_pos] != 0);

        float v = ap ? st : e;
        __nv_bfloat16 hi, lo; bf16_split(v, hi, lo);
        __nv_bfloat16* row = g_A + (size_t)m * 64;
        row[k] = hi; row[16 + k] = hi; row[32 + k] = lo;
        row[48 + k] = __float2bfloat16(k < 2 ? 1.f : 0.f);
    } else {
        int v = (blockIdx.x - prepBlocks) * 256 + threadIdx.x;
        if (v >= V) return;
        const float* wr = Wout + (size_t)v * 16;
        __nv_bfloat16* row = g_W + (size_t)v * 64;
#pragma unroll
        for (int k = 0; k < 16; k++) {
            __nv_bfloat16 hi, lo; bf16_split(wr[k], hi, lo);
            row[k] = hi; row[16 + k] = lo; row[32 + k] = hi;
        }
        __nv_bfloat16 bh, bl; bf16_split(bout[v], bh, bl);
        row[48] = bh; row[49] = bl;
#pragma unroll
        for (int k = 50; k < 64; k++) row[k] = __float2bfloat16(0.0f);
    }
}

// ---------------------------------------------------------------------------
// Kernel 2: HMMA bf16 GEMM (mma.sync.m16n8k16), tile 128x128, 8 warps (2x4).
// smem tiles use 72-bf16 (144B) row stride (ldmatrix conflict-free).
// Epilogue: shuffle-paired. One shfl.xor(1) exchange per nt-tile pair turns
// each quad's float2 fragments into full float4s (even lanes own cols 0-7 of
// tile 2t, odd lanes cols 8-15 of tile 2t+1) -> STG.128, halving store
// instructions and wavefronts vs direct float2 fragment stores. No smem, no
// extra syncs (R9's staged epilogue regressed: STS bank conflicts + syncs).
// ---------------------------------------------------------------------------
#define SA 72   // smem row stride in bf16

__global__ __launch_bounds__(256)
void hmma_gemm_kernel(float* __restrict__ out, int V) {
    __shared__ __align__(16) __nv_bfloat16 sA[128 * SA];
    __shared__ __align__(16) __nv_bfloat16 sB[128 * SA];

    int tid = threadIdx.x, wid = tid >> 5, lane = tid & 31;
    int row0 = blockIdx.y * 128;
    int v0   = blockIdx.x * 128;

    // cooperative tile loads: 128 rows x 64 bf16 = 1024 uint4 each
    {
        const uint4* srcA = (const uint4*)(g_A + (size_t)row0 * 64);
        const uint4* srcB = (const uint4*)(g_W + (size_t)v0 * 64);
#pragma unroll
        for (int i = tid; i < 1024; i += 256) {
            int r = i >> 3, c = i & 7;
            *(uint4*)(sA + r * SA + c * 8) = srcA[i];
            *(uint4*)(sB + r * SA + c * 8) = srcB[i];
        }
    }
    __syncthreads();

    int wm = wid >> 2;        // 0..1 : 64-row half
    int wn = wid & 3;         // 0..3 : 32-col quarter

    // ldmatrix lane->address mapping
    int aRowL = (lane & 7) + ((lane >> 3) & 1) * 8;
    int aColH = ((lane >> 4) & 1) * 8;
    int lb = lane & 15;
    int bRowL = lb & 7;
    int bColH = ((lb >> 3) & 1) * 8;

    uint32_t aBase = smem_u32(sA);
    uint32_t bBase = smem_u32(sB);

    float c[4][4][4];
#pragma unroll
    for (int mt = 0; mt < 4; mt++)
#pragma unroll
        for (int nt = 0; nt < 4; nt++)
#pragma unroll
            for (int j = 0; j < 4; j++) c[mt][nt][j] = 0.f;

#pragma unroll
    for (int k = 0; k < 4; k++) {
        uint32_t a[4][4], b[4][2];
#pragma unroll
        for (int mt = 0; mt < 4; mt++) {
            uint32_t addr = aBase +
                (uint32_t)(((wm * 64 + mt * 16 + aRowL) * SA + k * 16 + aColH) * 2);
            asm volatile("ldmatrix.sync.aligned.m8n8.x4.shared.b16 {%0,%1,%2,%3}, [%4];"
                         : "=r"(a[mt][0]), "=r"(a[mt][1]), "=r"(a[mt][2]), "=r"(a[mt][3])
                         : "r"(addr));
        }
#pragma unroll
        for (int nt = 0; nt < 4; nt++) {
            uint32_t addr = bBase +
                (uint32_t)(((wn * 32 + nt * 8 + bRowL) * SA + k * 16 + bColH) * 2);
            asm volatile("ldmatrix.sync.aligned.m8n8.x2.shared.b16 {%0,%1}, [%2];"
                         : "=r"(b[nt][0]), "=r"(b[nt][1]) : "r"(addr));
        }
#pragma unroll
        for (int mt = 0; mt < 4; mt++)
#pragma unroll
            for (int nt = 0; nt < 4; nt++)
                asm volatile(
                    "mma.sync.aligned.m16n8k16.row.col.f32.bf16.bf16.f32 "
                    "{%0,%1,%2,%3}, {%4,%5,%6,%7}, {%8,%9}, {%0,%1,%2,%3};"
                    : "+f"(c[mt][nt][0]), "+f"(c[mt][nt][1]),
                      "+f"(c[mt][nt][2]), "+f"(c[mt][nt][3])
                    : "r"(a[mt][0]), "r"(a[mt][1]), "r"(a[mt][2]), "r"(a[mt][3]),
                      "r"(b[nt][0]), "r"(b[nt][1]));
    }

    // ---------------- shuffle-paired epilogue -------------------------------
    // fragment: rows rr=lane/4 (+8), cols q2=(lane%4)*2 (+1) within each nt
    int rr = lane >> 2;
    int q2 = (lane & 3) * 2;
    bool evn = ((lane & 1) == 0);     // q2 in {0,4} ; odd: q2 in {2,6}
#pragma unroll
    for (int mt = 0; mt < 4; mt++) {
#pragma unroll
        for (int ntp = 0; ntp < 2; ntp++) {
#pragma unroll
            for (int h2 = 0; h2 < 2; h2++) {
                float a0 = c[mt][2*ntp][h2*2],   a1 = c[mt][2*ntp][h2*2+1];
                float b0 = c[mt][2*ntp+1][h2*2], b1 = c[mt][2*ntp+1][h2*2+1];
                float ra0 = __shfl_xor_sync(0xffffffffu, a0, 1);
                float ra1 = __shfl_xor_sync(0xffffffffu, a1, 1);
                float rb0 = __shfl_xor_sync(0xffffffffu, b0, 1);
                float rb1 = __shfl_xor_sync(0xffffffffu, b1, 1);
                float4 f4;
                int colbase;
                if (evn) {
                    // own tile-2ntp cols {q2,q2+1}, partner (q2+2) supplies {q2+2,q2+3}
                    f4 = make_float4(a0, a1, ra0, ra1);
                    colbase = 16 * ntp + q2;              // {0,4}
                } else {
                    // partner (q2-2) supplies tile-(2ntp+1) cols {q2-2,q2-1}, own {q2,q2+1}
                    f4 = make_float4(rb0, rb1, b0, b1);
                    colbase = 16 * ntp + 8 + (q2 - 2);    // 8 + {0,4}
                }
                int grow = row0 + wm * 64 + mt * 16 + rr + h2 * 8;
                int gcol = v0 + wn * 32 + colbase;
                __stcs((float4*)(out + (size_t)grow * V + gcol), f4);
            }
        }
    }
}

// ---------------------------------------------------------------------------
// Launch
// ---------------------------------------------------------------------------
extern "C" void kernel_launch(void* const* d_in, const int* in_sizes, int n_in,
                              void* d_out, int out_size) {
    const int*   ids   = (const int*)d_in[0];
    const int*   mask  = (const int*)d_in[1];
    const float* We    = (const float*)d_in[2];
    const float* gates = (const float*)d_in[3];
    const float* Wout  = (const float*)d_in[4];
    const float* bout  = (const float*)d_in[5];
    float* out = (float*)d_out;

    int BS    = in_sizes[0];          // 4096
    int V     = in_sizes[5];          // 32000
    int depth = in_sizes[3] / 256;    // 2
    int S     = 2048;
    int B     = BS / S;

    int prepBlocks  = (BS + 15) / 16;           // 256 (16 tokens per block)
    int wconvBlocks = (V + 255) / 256;          // 125
    prep_all_kernel<<<prepBlocks + wconvBlocks, 256>>>(
        ids, mask, We, gates, Wout, bout, BS, depth, S, B, V, prepBlocks);

    dim3 grid(V / 128, BS / 128);     // (250, 32)
    hmma_gemm_kernel<<<grid, 256>>>(out, V);
}

// round 11
// speedup vs baseline: 1.6406x; 1.0560x over previous
#include <cuda_runtime.h>
#include <cuda_bf16.h>
#include <cstdint>

typedef unsigned long long ull;

// ---------------------------------------------------------------------------
// Scratch (bf16 hi/lo-split GEMM operands, K=48 per row = 96 B)
//   g_A[m][48]: [Phi(16) | Phi(16) | Plo(16)]
//   g_W[v][48]: [Whi(16) | Wlo(16) | Whi(16)]
// D = Phi*Whi + Phi*Wlo + Plo*Whi (+ bias in epilogue); lo*lo term ~2^-18
// ---------------------------------------------------------------------------
__device__ __align__(16) __nv_bfloat16 g_A[4096 * 48];
__device__ __align__(16) __nv_bfloat16 g_W[32000 * 48];

__device__ __forceinline__ uint32_t smem_u32(const void* p) {
    uint32_t a;
    asm("{ .reg .u64 t; cvta.to.shared.u64 t, %1; cvt.u32.u64 %0, t; }"
        : "=r"(a) : "l"(p));
    return a;
}
__device__ __forceinline__ void bf16_split(float x, __nv_bfloat16& hi, __nv_bfloat16& lo) {
    hi = __float2bfloat16(x);
    lo = __float2bfloat16(x - __bfloat162float(hi));
}

// ---------------------------------------------------------------------------
// Kernel 1 (fused): blocks [0, prepBlocks): half-warp-per-token circuit -> g_A
//                   blocks [prepBlocks, ...): W_out conversion        -> g_W
// ---------------------------------------------------------------------------
__global__ __launch_bounds__(256)
void prep_all_kernel(const int* __restrict__ ids,
                     const int* __restrict__ mask,
                     const float* __restrict__ We,
                     const float* __restrict__ gates,
                     const float* __restrict__ Wout,
                     int BS, int depth, int S, int B, int V, int prepBlocks) {
    if (blockIdx.x < (unsigned)prepBlocks) {
        __shared__ float sgt[2 * 256];   // transposed: sgt[l*256 + d*16 + o]
        for (int i = threadIdx.x; i < depth * 256; i += 256) {
            int l = i >> 8, r = i & 255, o = r >> 4, d = r & 15;
            sgt[l * 256 + d * 16 + o] = gates[i];
        }
        __syncthreads();

        int lane = threadIdx.x & 31, wid = threadIdx.x >> 5;
        int half = lane >> 4, k = lane & 15;
        int m = blockIdx.x * 16 + wid * 2 + half;
        if (m >= BS) return;

        int tok = ids[m];
        float e = We[(size_t)tok * 16 + k];
        float s = e * e;
#pragma unroll
        for (int off = 8; off; off >>= 1)
            s += __shfl_xor_sync(0xffffffffu, s, off, 16);
        e *= 1.f / (sqrtf(s) + 1e-12f);
        float st = e;

        for (int l = 0; l < depth; l++) {
            float acc = 0.f;
            const float* g = sgt + l * 256 + k;
#pragma unroll
            for (int d = 0; d < 16; d++) {
                float sd = __shfl_sync(0xffffffffu, st, d, 16);
                acc = fmaf(sd, g[d * 16], acc);
            }
            float x = acc * (0.99f * 0.99f) + (0.01f / 16.f);
            float s2 = x * x;
#pragma unroll
            for (int off = 8; off; off >>= 1)
                s2 += __shfl_xor_sync(0xffffffffu, s2, off, 16);
            st = x * (1.f / (sqrtf(s2) + 1e-12f));
        }
        st = st * 0.99f + (0.01f / 16.f);

        int s_pos = m % S;
        bool ap = true;
        for (int b = 0; b < B; b++) ap = ap && (mask[b * S + s_pos] != 0);

        float v = ap ? st : e;
        __nv_bfloat16 hi, lo; bf16_split(v, hi, lo);
        __nv_bfloat16* row = g_A + (size_t)m * 48;
        row[k] = hi; row[16 + k] = hi; row[32 + k] = lo;
    } else {
        int v = (blockIdx.x - prepBlocks) * 256 + threadIdx.x;
        if (v >= V) return;
        const float* wr = Wout + (size_t)v * 16;
        __nv_bfloat16* row = g_W + (size_t)v * 48;
#pragma unroll
        for (int k = 0; k < 16; k++) {
            __nv_bfloat16 hi, lo; bf16_split(wr[k], hi, lo);
            row[k] = hi; row[16 + k] = lo; row[32 + k] = hi;
        }
    }
}

// ---------------------------------------------------------------------------
// Kernel 2: HMMA bf16 GEMM (mma.sync.m16n8k16), tile 128x128, 8 warps (2x4).
// K=48 (3 k-steps, 25% less ldmatrix/MMA/tile traffic than K=64-with-bias).
// smem tiles: 56-bf16 (112B) row stride -> r*112 mod 128 spans 8 distinct
// 16B groups, ldmatrix conflict-free; tiles 2x14KB -> 2 CTAs/SM.
// Bias added in epilogue from a 512B smem table (broadcast LDS).
// Epilogue: shuffle-paired float4 stores (proven in R10).
// ---------------------------------------------------------------------------
#define SA 56   // smem row stride in bf16

__global__ __launch_bounds__(256, 2)
void hmma_gemm_kernel(const float* __restrict__ bout,
                      float* __restrict__ out, int V) {
    __shared__ __align__(16) __nv_bfloat16 sA[128 * SA];
    __shared__ __align__(16) __nv_bfloat16 sB[128 * SA];
    __shared__ __align__(16) float s_bias[128];

    int tid = threadIdx.x, wid = tid >> 5, lane = tid & 31;
    int row0 = blockIdx.y * 128;
    int v0   = blockIdx.x * 128;

    // cooperative tile loads: 128 rows x 48 bf16 = 768 uint4 each (3/thread)
    {
        const uint4* srcA = (const uint4*)(g_A + (size_t)row0 * 48);
        const uint4* srcB = (const uint4*)(g_W + (size_t)v0 * 48);
#pragma unroll
        for (int i = tid; i < 768; i += 256) {
            int r = i / 6, c = i % 6;
            *(uint4*)(sA + r * SA + c * 8) = srcA[i];
            *(uint4*)(sB + r * SA + c * 8) = srcB[i];
        }
        if (tid < 32) ((float4*)s_bias)[tid] = ((const float4*)(bout + v0))[tid];
    }
    __syncthreads();

    int wm = wid >> 2;        // 0..1 : 64-row half
    int wn = wid & 3;         // 0..3 : 32-col quarter

    // ldmatrix lane->address mapping
    int aRowL = (lane & 7) + ((lane >> 3) & 1) * 8;
    int aColH = ((lane >> 4) & 1) * 8;
    int lb = lane & 15;
    int bRowL = lb & 7;
    int bColH = ((lb >> 3) & 1) * 8;

    uint32_t aBase = smem_u32(sA);
    uint32_t bBase = smem_u32(sB);

    float c[4][4][4];
#pragma unroll
    for (int mt = 0; mt < 4; mt++)
#pragma unroll
        for (int nt = 0; nt < 4; nt++)
#pragma unroll
            for (int j = 0; j < 4; j++) c[mt][nt][j] = 0.f;

#pragma unroll
    for (int k = 0; k < 3; k++) {
        uint32_t a[4][4], b[4][2];
#pragma unroll
        for (int mt = 0; mt < 4; mt++) {
            uint32_t addr = aBase +
                (uint32_t)(((wm * 64 + mt * 16 + aRowL) * SA + k * 16 + aColH) * 2);
            asm volatile("ldmatrix.sync.aligned.m8n8.x4.shared.b16 {%0,%1,%2,%3}, [%4];"
                         : "=r"(a[mt][0]), "=r"(a[mt][1]), "=r"(a[mt][2]), "=r"(a[mt][3])
                         : "r"(addr));
        }
#pragma unroll
        for (int nt = 0; nt < 4; nt++) {
            uint32_t addr = bBase +
                (uint32_t)(((wn * 32 + nt * 8 + bRowL) * SA + k * 16 + bColH) * 2);
            asm volatile("ldmatrix.sync.aligned.m8n8.x2.shared.b16 {%0,%1}, [%2];"
                         : "=r"(b[nt][0]), "=r"(b[nt][1]) : "r"(addr));
        }
#pragma unroll
        for (int mt = 0; mt < 4; mt++)
#pragma unroll
            for (int nt = 0; nt < 4; nt++)
                asm volatile(
                    "mma.sync.aligned.m16n8k16.row.col.f32.bf16.bf16.f32 "
                    "{%0,%1,%2,%3}, {%4,%5,%6,%7}, {%8,%9}, {%0,%1,%2,%3};"
                    : "+f"(c[mt][nt][0]), "+f"(c[mt][nt][1]),
                      "+f"(c[mt][nt][2]), "+f"(c[mt][nt][3])
                    : "r"(a[mt][0]), "r"(a[mt][1]), "r"(a[mt][2]), "r"(a[mt][3]),
                      "r"(b[nt][0]), "r"(b[nt][1]));
    }

    // bias add (per original column ownership, before the shuffle exchange)
    int rr = lane >> 2;
    int q2 = (lane & 3) * 2;
#pragma unroll
    for (int nt = 0; nt < 4; nt++) {
        float2 bv = *(const float2*)(s_bias + wn * 32 + nt * 8 + q2);
#pragma unroll
        for (int mt = 0; mt < 4; mt++) {
            c[mt][nt][0] += bv.x; c[mt][nt][1] += bv.y;
            c[mt][nt][2] += bv.x; c[mt][nt][3] += bv.y;
        }
    }

    // ---------------- shuffle-paired epilogue (R10) --------------------------
    bool evn = ((lane & 1) == 0);
#pragma unroll
    for (int mt = 0; mt < 4; mt++) {
#pragma unroll
        for (int ntp = 0; ntp < 2; ntp++) {
#pragma unroll
            for (int h2 = 0; h2 < 2; h2++) {
                float a0 = c[mt][2*ntp][h2*2],   a1 = c[mt][2*ntp][h2*2+1];
                float b0 = c[mt][2*ntp+1][h2*2], b1 = c[mt][2*ntp+1][h2*2+1];
                float ra0 = __shfl_xor_sync(0xffffffffu, a0, 1);
                float ra1 = __shfl_xor_sync(0xffffffffu, a1, 1);
                float rb0 = __shfl_xor_sync(0xffffffffu, b0, 1);
                float rb1 = __shfl_xor_sync(0xffffffffu, b1, 1);
                float4 f4;
                int colbase;
                if (evn) {
                    f4 = make_float4(a0, a1, ra0, ra1);
                    colbase = 16 * ntp + q2;
                } else {
                    f4 = make_float4(rb0, rb1, b0, b1);
                    colbase = 16 * ntp + 8 + (q2 - 2);
                }
                int grow = row0 + wm * 64 + mt * 16 + rr + h2 * 8;
                int gcol = v0 + wn * 32 + colbase;
                __stcs((float4*)(out + (size_t)grow * V + gcol), f4);
            }
        }
    }
}

// ---------------------------------------------------------------------------
// Launch
// ---------------------------------------------------------------------------
extern "C" void kernel_launch(void* const* d_in, const int* in_sizes, int n_in,
                              void* d_out, int out_size) {
    const int*   ids   = (const int*)d_in[0];
    const int*   mask  = (const int*)d_in[1];
    const float* We    = (const float*)d_in[2];
    const float* gates = (const float*)d_in[3];
    const float* Wout  = (const float*)d_in[4];
    const float* bout  = (const float*)d_in[5];
    float* out = (float*)d_out;

    int BS    = in_sizes[0];          // 4096
    int V     = in_sizes[5];          // 32000
    int depth = in_sizes[3] / 256;    // 2
    int S     = 2048;
    int B     = BS / S;

    int prepBlocks  = (BS + 15) / 16;           // 256 (16 tokens per block)
    int wconvBlocks = (V + 255) / 256;          // 125
    prep_all_kernel<<<prepBlocks + wconvBlocks, 256>>>(
        ids, mask, We, gates, Wout, BS, depth, S, B, V, prepBlocks);

    dim3 grid(V / 128, BS / 128);     // (250, 32)
    hmma_gemm_kernel<<<grid, 256>>>(bout, out, V);
}